// round 13
// baseline (speedup 1.0000x reference)
#include <cuda_runtime.h>
#include <math.h>
#include <stdint.h>

#define CS   8
#define TPB  512
#define HID  256
#define ENCL 16
#define DECL 25
#define NV   28

typedef unsigned long long ull;
#define FULLM 0xffffffffu

// projection tables, layout [t][unit 0..255][gate 0..3]
__device__ float g_pre[ENCL * 1024];
__device__ float g_tab[NV * 1024];
__device__ int   g_flag[64];         // [0..31] enc CTA done, [32..63] dec CTA done

// ---------------- smem layout (float offsets) ----------------
#define O_H3B   0               // 3 x 256 h ring
#define O_CF    768             // cfull [256]
#define O_PRE   1024            // [16][32 units][4 gates] = 2048
#define O_TAB   3072            // [28][32][4] = 3584
#define O_CATH  6656            // [40]
#define O_CATC  6696            // [40]
#define O_CNEW  6736            // [32]
#define O_WMAX  6768            // 2 phases x 16 ull = 64 floats
#define O_TAGS  6832            // 3 slots x 128 u32 = 384 floats
#define SMEM_FLOATS 7216
#define SMEM_BYTES  (SMEM_FLOATS * 4)

// ---------------- PTX helpers ----------------
__device__ __forceinline__ uint32_t smem_u32(const void* p) {
    uint32_t a;
    asm("{ .reg .u64 t; cvta.to.shared.u64 t, %1; cvt.u32.u64 %0, t; }" : "=r"(a) : "l"(p));
    return a;
}
__device__ __forceinline__ uint32_t mapa_u32(uint32_t a, uint32_t rank) {
    uint32_t r;
    asm("mapa.shared::cluster.u32 %0, %1, %2;" : "=r"(r) : "r"(a), "r"(rank));
    return r;
}
__device__ __forceinline__ void st_cluster_b64(uint32_t addr, ull v) {
    asm volatile("st.shared::cluster.b64 [%0], %1;" :: "r"(addr), "l"(v) : "memory");
}
__device__ __forceinline__ void st_rel_cluster_u32(uint32_t addr, uint32_t v) {
    asm volatile("st.release.cluster.shared::cluster.u32 [%0], %1;" :: "r"(addr), "r"(v) : "memory");
}
__device__ __forceinline__ void cluster_bar() {
    asm volatile("barrier.cluster.arrive.aligned;" ::: "memory");
    asm volatile("barrier.cluster.wait.aligned;" ::: "memory");
}
__device__ __forceinline__ int ld_acq_gpu(const int* p) {
    int v;
    asm volatile("ld.acquire.gpu.global.s32 %0, [%1];" : "=r"(v) : "l"(p) : "memory");
    return v;
}
__device__ __forceinline__ void st_rel_gpu(int* p, int v) {
    asm volatile("st.release.gpu.global.s32 [%0], %1;" :: "l"(p), "r"(v) : "memory");
}
// poll 128 tag words of a slot: lane reads 4 contiguous, all >= n
__device__ __forceinline__ void poll_tags(uint32_t tagsb, int slot, int lane, int n) {
    uint32_t a = tagsb + (uint32_t)(slot * 512 + lane * 16);
    for (;;) {
        int x, y, z, u;
        asm volatile("ld.volatile.shared.v4.u32 {%0,%1,%2,%3}, [%4];"
                     : "=r"(x), "=r"(y), "=r"(z), "=r"(u) : "r"(a) : "memory");
        int ok = (x >= n) & (y >= n) & (z >= n) & (u >= n);
        if (__all_sync(FULLM, ok)) break;
    }
}
__device__ __forceinline__ void ffma2(ull &acc, ull a, ull b) {
    asm("fma.rn.f32x2 %0, %1, %2, %0;" : "+l"(acc) : "l"(a), "l"(b));
}
__device__ __forceinline__ float ups(ull a) {
    float lo, hi;
    asm("mov.b64 {%0,%1}, %2;" : "=f"(lo), "=f"(hi) : "l"(a));
    return lo + hi;
}
__device__ __forceinline__ ull pack2(float lo, float hi) {
    ull r;
    asm("mov.b64 %0, {%1,%2};" : "=l"(r) : "f"(lo), "f"(hi));
    return r;
}
__device__ __forceinline__ float sigf(float x) { return __fdividef(1.f, 1.f + __expf(-x)); }
__device__ __forceinline__ float tanhfast(float x) {
    float t = __expf(-2.f * fabsf(x));
    return copysignf(__fdividef(1.f - t, 1.f + t), x);
}
__device__ __forceinline__ float red32(float s) {
#pragma unroll
    for (int o = 16; o > 0; o >>= 1) s += __shfl_xor_sync(FULLM, s, o);
    return s;
}
__device__ __forceinline__ float dot8(float4 a0, float4 a1, float4 b0, float4 b1) {
    return a0.x*b0.x + a0.y*b0.y + a0.z*b0.z + a0.w*b0.w
         + a1.x*b1.x + a1.y*b1.y + a1.z*b1.z + a1.w*b1.w;
}
__device__ __forceinline__ void pf_l2(const void* p) {
    asm volatile("prefetch.global.L2 [%0];" :: "l"(p));
}

// 8 gate-row weight chunks (lane's 8 h-elems) for this warp
__device__ __forceinline__ void load_w8(const float* W, int b, int w, int lane, ull wr[8][4]) {
#pragma unroll
    for (int r = 0; r < 8; r++) {
        int row = (r & 3) * HID + b * 32 + 2 * w + (r >> 2);
        const ulonglong2* p = (const ulonglong2*)(W + row * HID + 8 * lane);
        ulonglong2 v0 = p[0], v1 = p[1];
        wr[r][0] = v0.x; wr[r][1] = v0.y; wr[r][2] = v1.x; wr[r][3] = v1.y;
    }
}

// multi-acc butterfly: 8 partials/lane -> every lane holds total of acc (lane&7)
__device__ __forceinline__ float reduce8(float a0, float a1, float a2, float a3,
                                         float a4, float a5, float a6, float a7, int lane) {
    a0 += __shfl_xor_sync(FULLM, a0, 16); a1 += __shfl_xor_sync(FULLM, a1, 16);
    a2 += __shfl_xor_sync(FULLM, a2, 16); a3 += __shfl_xor_sync(FULLM, a3, 16);
    a4 += __shfl_xor_sync(FULLM, a4, 16); a5 += __shfl_xor_sync(FULLM, a5, 16);
    a6 += __shfl_xor_sync(FULLM, a6, 16); a7 += __shfl_xor_sync(FULLM, a7, 16);
    a0 += __shfl_xor_sync(FULLM, a0, 8);  a1 += __shfl_xor_sync(FULLM, a1, 8);
    a2 += __shfl_xor_sync(FULLM, a2, 8);  a3 += __shfl_xor_sync(FULLM, a3, 8);
    a4 += __shfl_xor_sync(FULLM, a4, 8);  a5 += __shfl_xor_sync(FULLM, a5, 8);
    a6 += __shfl_xor_sync(FULLM, a6, 8);  a7 += __shfl_xor_sync(FULLM, a7, 8);
    bool b2 = (lane >> 2) & 1;
    float s0 = b2 ? a0 : a4, s1 = b2 ? a1 : a5, s2 = b2 ? a2 : a6, s3 = b2 ? a3 : a7;
    float r0 = __shfl_xor_sync(FULLM, s0, 4), r1 = __shfl_xor_sync(FULLM, s1, 4);
    float r2 = __shfl_xor_sync(FULLM, s2, 4), r3 = __shfl_xor_sync(FULLM, s3, 4);
    float k0 = (b2 ? a4 : a0) + r0, k1 = (b2 ? a5 : a1) + r1;
    float k2 = (b2 ? a6 : a2) + r2, k3 = (b2 ? a7 : a3) + r3;
    bool b1 = (lane >> 1) & 1;
    float t0 = b1 ? k0 : k2, t1 = b1 ? k1 : k3;
    float u0 = __shfl_xor_sync(FULLM, t0, 2), u1 = __shfl_xor_sync(FULLM, t1, 2);
    float m0 = (b1 ? k2 : k0) + u0, m1 = (b1 ? k3 : k1) + u1;
    bool b0 = lane & 1;
    float sv = b0 ? m0 : m1;
    float rv = __shfl_xor_sync(FULLM, sv, 1);
    return (b0 ? m1 : m0) + rv;
}
// 2-acc reduce: every lane gets total of acc (lane&1)
__device__ __forceinline__ float reduce2(float l0, float l1, int lane) {
    l0 += __shfl_xor_sync(FULLM, l0, 16); l1 += __shfl_xor_sync(FULLM, l1, 16);
    l0 += __shfl_xor_sync(FULLM, l0, 8);  l1 += __shfl_xor_sync(FULLM, l1, 8);
    l0 += __shfl_xor_sync(FULLM, l0, 4);  l1 += __shfl_xor_sync(FULLM, l1, 4);
    l0 += __shfl_xor_sync(FULLM, l0, 2);  l1 += __shfl_xor_sync(FULLM, l1, 2);
    bool b0 = lane & 1;
    float s = b0 ? l0 : l1;
    float r = __shfl_xor_sync(FULLM, s, 1);
    return (b0 ? l1 : l0) + r;
}

// ================= kernel 1: tables (64 CTAs; enc/dec halves in PARALLEL) =================
__global__ void __launch_bounds__(256) table_kernel(
    const int* data,
    const float* enc_Wih, const float* enc_bih, const float* enc_bhh, const float* enc_emb,
    const float* dec_Wih, const float* dec_bih, const float* dec_bhh, const float* dec_emb)
{
    __shared__ __align__(16) float xs[NV * HID];
    const int tid  = threadIdx.x;
    const int w    = tid >> 5;
    const int lane = tid & 31;
    const int g    = blockIdx.x;

    if (g < 32) {
        for (int i = tid; i < ENCL * 64; i += 256) {
            int t = i >> 6, c4 = i & 63;
            ((float4*)xs)[i] = ((const float4*)(enc_emb + data[t] * HID))[c4];
        }
        __syncthreads();
        int Rb = g * 32 + w * 4;
        float4 aw[4][2]; float bias[4];
#pragma unroll
        for (int r = 0; r < 4; r++) {
            const float4* p = (const float4*)(enc_Wih + (Rb + r) * HID);
            aw[r][0] = p[lane * 2]; aw[r][1] = p[lane * 2 + 1];
            bias[r] = enc_bih[Rb + r] + enc_bhh[Rb + r];
        }
#pragma unroll 1
        for (int t = 0; t < ENCL; t++) {
            const float4* xv = (const float4*)(xs + t * HID) + lane * 2;
            float4 x0 = xv[0], x1 = xv[1];
#pragma unroll
            for (int r = 0; r < 4; r++) {
                float s = red32(dot8(aw[r][0], aw[r][1], x0, x1));
                if (lane == 0) {
                    int R = Rb + r;
                    g_pre[t * 1024 + (R & 255) * 4 + (R >> 8)] = s + bias[r];
                }
            }
        }
        __syncthreads();
        if (tid == 0) st_rel_gpu(&g_flag[g], 1);
    } else {
        for (int i = tid; i < NV * 64; i += 256) {
            int tk = i >> 6, c4 = i & 63;
            float4 v = ((const float4*)(dec_emb + tk * HID))[c4];
            v.x = fmaxf(v.x, 0.f); v.y = fmaxf(v.y, 0.f);
            v.z = fmaxf(v.z, 0.f); v.w = fmaxf(v.w, 0.f);
            ((float4*)xs)[i] = v;
        }
        __syncthreads();
        int Rb = (g - 32) * 32 + w * 4;
        float4 aw[4][2]; float bias[4];
#pragma unroll
        for (int r = 0; r < 4; r++) {
            const float4* p = (const float4*)(dec_Wih + (Rb + r) * HID);
            aw[r][0] = p[lane * 2]; aw[r][1] = p[lane * 2 + 1];
            bias[r] = dec_bih[Rb + r] + dec_bhh[Rb + r];
        }
#pragma unroll 1
        for (int tk = 0; tk < NV; tk++) {
            const float4* xv = (const float4*)(xs + tk * HID) + lane * 2;
            float4 x0 = xv[0], x1 = xv[1];
#pragma unroll
            for (int r = 0; r < 4; r++) {
                float s = red32(dot8(aw[r][0], aw[r][1], x0, x1));
                if (lane == 0) {
                    int R = Rb + r;
                    g_tab[tk * 1024 + (R & 255) * 4 + (R >> 8)] = s + bias[r];
                }
            }
        }
        __syncthreads();
        if (tid == 0) st_rel_gpu(&g_flag[g], 1);
    }
}

// ================= kernel 2: barrier-free per-warp-tag LSTM =================
__global__ void __launch_bounds__(TPB, 1) __cluster_dims__(CS, 1, 1) vae_kernel(
    const int* data_c, const int* target_c, const float* cond_emb,
    const float* enc_Whh,
    const float* hmu_W, const float* hmu_b, const float* cmu_W, const float* cmu_b,
    const float* fc1_W, const float* fc1_b, const float* fc2_W, const float* fc2_b,
    const float* dec_Whh,
    const float* out_W, const float* out_b,
    float* out, int out_size)
{
    extern __shared__ __align__(16) float sm[];
    float* h3b    = sm + O_H3B;
    float* cfull  = sm + O_CF;
    float* pre_sh = sm + O_PRE;
    float* tab_sh = sm + O_TAB;
    float* cat_h  = sm + O_CATH;
    float* cat_c  = sm + O_CATC;
    float* cnew_sh= sm + O_CNEW;
    volatile ull* wmax_sh = (volatile ull*)(sm + O_WMAX);

    const int tid  = threadIdx.x;
    const int w    = tid >> 5;
    const int lane = tid & 31;
    const int b    = blockIdx.x;
    const int uu   = (lane >> 2) & 1;

    const uint32_t base   = smem_u32(sm);
    const uint32_t tagsb  = base + O_TAGS * 4;
    const uint32_t myrmap = mapa_u32(base, (uint32_t)(lane & 7));

    // encoder recurrent weights
    ull wr[8][4];
    load_w8(enc_Whh, b, w, lane, wr);

    // L2 prefetch serial-path weights
    for (int i = tid; i < 1024; i += TPB) {
        int gi = i >> 8, off = i & 255;
        pf_l2((const char*)(dec_Whh + (gi * 256 + b * 32) * HID) + off * 128);
    }
    for (int i = tid; i < 256; i += TPB) {
        pf_l2((const char*)hmu_W + i * 128);
        pf_l2((const char*)cmu_W + i * 128);
    }
    for (int i = tid; i < 320; i += TPB) {
        pf_l2((const char*)fc1_W + i * 128);
        pf_l2((const char*)fc2_W + i * 128);
    }
    for (int i = tid; i < 224; i += TPB)
        pf_l2((const char*)out_W + i * 128);

    // ---- h0 (slot 0) + c0 + tag/wmax init ----
    const int dcid = data_c[0], tcid = target_c[0];
    if (tid < HID) {
        float v = (tid >= HID - 8) ? cond_emb[dcid * 8 + (tid - (HID - 8))] : 0.f;
        h3b[tid] = v;
    }
    int ug = b * 32 + 2 * w + uu;
    float creg = (ug >= HID - 8) ? cond_emb[dcid * 8 + (ug - (HID - 8))] : 0.f;
    if (tid < 384) ((int*)(sm + O_TAGS))[tid] = 0;
    if (tid < 32) ((ull*)(sm + O_WMAX))[tid] = 0ull;

    // wait for enc table, copy slice
    if (tid < 32) while (ld_acq_gpu(&g_flag[tid]) == 0) { }
    __syncthreads();
    for (int i = tid; i < ENCL * 32; i += TPB)
        ((float4*)pre_sh)[i] = ((const float4*)g_pre)[(i >> 5) * 256 + b * 32 + (i & 31)];

    __syncthreads();
    cluster_bar();                                    // tag init visible before remote tags

    // ================= encoder: n = 0..15, NO barriers =================
#pragma unroll 1
    for (int n = 0; n < ENCL; n++) {
        int slot = n % 3, slot2 = (n + 1) % 3;
        poll_tags(tagsb, slot, lane, n);
        const ulonglong2* hp = (const ulonglong2*)(h3b + slot * HID);
        ulonglong2 X = hp[lane * 2], Y = hp[lane * 2 + 1];
        float a[8];
#pragma unroll
        for (int r = 0; r < 8; r++) {
            ull ac = 0ull;
            ffma2(ac, wr[r][0], X.x); ffma2(ac, wr[r][1], X.y);
            ffma2(ac, wr[r][2], Y.x); ffma2(ac, wr[r][3], Y.y);
            a[r] = ups(ac);
        }
        float tot = reduce8(a[0], a[1], a[2], a[3], a[4], a[5], a[6], a[7], lane);
        int gb = lane & 28;
        float g0 = __shfl_sync(FULLM, tot, gb);
        float g1 = __shfl_sync(FULLM, tot, gb | 1);
        float g2 = __shfl_sync(FULLM, tot, gb | 2);
        float g3 = __shfl_sync(FULLM, tot, gb | 3);
        float4 pr = *(const float4*)(pre_sh + n * 128 + (2 * w + uu) * 4);
        float gi = g0 + pr.x, gf = g1 + pr.y, gg = g2 + pr.z, go = g3 + pr.w;
        float c = sigf(gf) * creg + sigf(gi) * tanhfast(gg);
        float h = sigf(go) * tanhfast(c);
        creg = c;
        float hA = __shfl_sync(FULLM, h, 0);
        float hB = __shfl_sync(FULLM, h, 4);
        if (lane < 8) {
            ull hp2 = pack2(hA, hB);
            uint32_t off = (uint32_t)((slot2 * HID + b * 32 + 2 * w) * 4);
            st_cluster_b64(myrmap + off, hp2);
            if (n == ENCL - 1) {
                float cA = __shfl_sync(0xffu, creg, 0);
                float cB = __shfl_sync(0xffu, creg, 4);
                ull cp = pack2(cA, cB);
                uint32_t co = (uint32_t)((O_CF + b * 32 + 2 * w) * 4);
                st_cluster_b64(myrmap + co, cp);
            }
            uint32_t toff = (uint32_t)(O_TAGS * 4 + slot2 * 512 + (b * 16 + w) * 4);
            st_rel_cluster_u32(myrmap + toff, (uint32_t)(n + 1));
        }
    }

    // hT (slot 1, tag 16) + cfull — poll guarantees every warp everywhere is past step 15
    poll_tags(tagsb, 1, lane, ENCL);

    // ================= latent heads + decoder init =================
    {
        const float4* hv = (const float4*)(h3b + HID) + lane * 2;
        float4 h0v = hv[0], h1v = hv[1];
        const float4* cv = (const float4*)cfull + lane * 2;
        float4 c0v = cv[0], c1v = cv[1];
#pragma unroll
        for (int half = 0; half < 2; half++) {
            int rr = w + half * 16;
            const float4* pp = (const float4*)(hmu_W + rr * HID);
            float4 x0 = pp[lane * 2], x1 = pp[lane * 2 + 1];
            float s = red32(dot8(x0, x1, h0v, h1v));
            if (lane == 0) cat_h[rr] = s + hmu_b[rr];
            pp = (const float4*)(cmu_W + rr * HID);
            x0 = pp[lane * 2]; x1 = pp[lane * 2 + 1];
            s = red32(dot8(x0, x1, c0v, c1v));
            if (lane == 0) cat_c[rr] = s + cmu_b[rr];
        }
    }
    if (tid < 8) {
        float v = cond_emb[tcid * 8 + tid];
        cat_h[32 + tid] = v; cat_c[32 + tid] = v;
    }
    __syncthreads();
    float newv = 0.f;
    if (tid < HID) {
        float s = fc1_b[tid];
        const float* wrp = fc1_W + tid * 40;
#pragma unroll
        for (int k = 0; k < 40; k++) s += cat_h[k] * wrp[k];
        newv = s;
    }
    if (tid < 32) {
        int j = b * 32 + tid;
        float s = fc2_b[j];
        const float* wrp = fc2_W + j * 40;
#pragma unroll
        for (int k = 0; k < 40; k++) s += cat_c[k] * wrp[k];
        cnew_sh[tid] = s;
    }
    __syncthreads();
    if (tid < HID) h3b[2 * HID + tid] = newv;         // dh -> slot 2 (= h(17))
    if (tid < 128) ((int*)(sm + O_TAGS))[2 * 128 + tid] = 17;   // local slot-2 tags
    creg = cnew_sh[2 * w + uu];

    // decoder token table
    if (tid < 32) while (ld_acq_gpu(&g_flag[32 + tid]) == 0) { }
    __syncthreads();
    for (int i = tid; i < NV * 32; i += TPB)
        ((float4*)tab_sh)[i] = ((const float4*)g_tab)[(i >> 5) * 256 + b * 32 + (i & 31)];

    // decoder weights + out_W rows into registers
    load_w8(dec_Whh, b, w, lane, wr);
    ull owr[2][4];
    {
        int lw = (w < 14) ? w : 0;
#pragma unroll
        for (int rr = 0; rr < 2; rr++) {
            const ulonglong2* p = (const ulonglong2*)(out_W + (2 * lw + rr) * HID + 8 * lane);
            ulonglong2 v0 = p[0], v1 = p[1];
            owr[rr][0] = v0.x; owr[rr][1] = v0.y; owr[rr][2] = v1.x; owr[rr][3] = v1.y;
        }
    }
    float obv = (w < 14) ? out_b[2 * w + (lane & 1)] : 0.f;
    __syncthreads();

    // ================= decoder: N = 17..41, NO barriers =================
#pragma unroll 1
    for (int N = 17; N < 17 + DECL; N++) {
        int slot = N % 3, slot2 = (N + 1) % 3, ph = N & 1;
        poll_tags(tagsb, slot, lane, N);
        const ulonglong2* hp = (const ulonglong2*)(h3b + slot * HID);
        ulonglong2 X = hp[lane * 2], Y = hp[lane * 2 + 1];

        float lgv = 0.f;
        if (w < 14 && N > 17) {
            ull la0 = 0ull, la1 = 0ull;
            ffma2(la0, owr[0][0], X.x); ffma2(la0, owr[0][1], X.y);
            ffma2(la0, owr[0][2], Y.x); ffma2(la0, owr[0][3], Y.y);
            ffma2(la1, owr[1][0], X.x); ffma2(la1, owr[1][1], X.y);
            ffma2(la1, owr[1][2], Y.x); ffma2(la1, owr[1][3], Y.y);
            lgv = reduce2(ups(la0), ups(la1), lane) + obv;
            uint32_t bits = __float_as_uint(lgv);
            uint32_t key = (bits & 0x80000000u) ? ~bits : (bits | 0x80000000u);
            int row = 2 * w + (lane & 1);
            ull cmp = ((ull)key << 16) | ((ull)(255 - row) << 8) | (ull)(N & 0xff);
            ull c1 = __shfl_xor_sync(FULLM, cmp, 1);
            if (c1 > cmp) cmp = c1;
            if (lane == 0) wmax_sh[ph * 16 + w] = cmp;
        }

        float a[8];
#pragma unroll
        for (int r = 0; r < 8; r++) {
            ull ac = 0ull;
            ffma2(ac, wr[r][0], X.x); ffma2(ac, wr[r][1], X.y);
            ffma2(ac, wr[r][2], Y.x); ffma2(ac, wr[r][3], Y.y);
            a[r] = ups(ac);
        }
        float tot = reduce8(a[0], a[1], a[2], a[3], a[4], a[5], a[6], a[7], lane);

        int tok = 0;
        if (N > 17) {
            ull v;
            for (;;) {                                 // spin until all 14 wmax words current
                v = (lane < 14) ? wmax_sh[ph * 16 + lane] : 0ull;
                int ok = (lane < 14) ? ((int)(v & 0xffu) == (N & 0xff)) : 1;
                if (__all_sync(FULLM, ok)) break;
            }
            if (lane >= 14) v = 0ull;
#pragma unroll
            for (int o = 1; o < 32; o <<= 1) {
                ull ot = __shfl_xor_sync(FULLM, v, o);
                if (ot > v) v = ot;
            }
            tok = 255 - (int)((v >> 8) & 0xffu);
            if (b == 0) {
                if (w < 14 && lane < 2) out[(N - 18) * NV + 2 * w + lane] = lgv;
                if (w == 15 && lane == 0) out[NV * DECL + (N - 18)] = (float)tok;
            }
        }

        int gb = lane & 28;
        float g0 = __shfl_sync(FULLM, tot, gb);
        float g1 = __shfl_sync(FULLM, tot, gb | 1);
        float g2 = __shfl_sync(FULLM, tot, gb | 2);
        float g3 = __shfl_sync(FULLM, tot, gb | 3);
        float4 pr = *(const float4*)(tab_sh + tok * 128 + (2 * w + uu) * 4);
        float gi = g0 + pr.x, gf = g1 + pr.y, gg = g2 + pr.z, go = g3 + pr.w;
        float c = sigf(gf) * creg + sigf(gi) * tanhfast(gg);
        float h = sigf(go) * tanhfast(c);
        creg = c;
        float hA = __shfl_sync(FULLM, h, 0);
        float hB = __shfl_sync(FULLM, h, 4);
        if (lane < 8) {
            ull hp2 = pack2(hA, hB);
            uint32_t off = (uint32_t)((slot2 * HID + b * 32 + 2 * w) * 4);
            st_cluster_b64(myrmap + off, hp2);
            uint32_t toff = (uint32_t)(O_TAGS * 4 + slot2 * 512 + (b * 16 + w) * 4);
            st_rel_cluster_u32(myrmap + toff, (uint32_t)(N + 1));
        }
    }

    // ---- tail: logits/argmax of h(42) (slot 0, tag 42), rank 0 only ----
    if (b == 0) {
        poll_tags(tagsb, 0, lane, 42);
        const ulonglong2* hp = (const ulonglong2*)h3b;
        ulonglong2 X = hp[lane * 2], Y = hp[lane * 2 + 1];
        if (w < 14) {
            ull la0 = 0ull, la1 = 0ull;
            ffma2(la0, owr[0][0], X.x); ffma2(la0, owr[0][1], X.y);
            ffma2(la0, owr[0][2], Y.x); ffma2(la0, owr[0][3], Y.y);
            ffma2(la1, owr[1][0], X.x); ffma2(la1, owr[1][1], X.y);
            ffma2(la1, owr[1][2], Y.x); ffma2(la1, owr[1][3], Y.y);
            float lgv = reduce2(ups(la0), ups(la1), lane) + obv;
            uint32_t bits = __float_as_uint(lgv);
            uint32_t key = (bits & 0x80000000u) ? ~bits : (bits | 0x80000000u);
            int row = 2 * w + (lane & 1);
            ull cmp = ((ull)key << 16) | ((ull)(255 - row) << 8) | 42ull;
            ull c1 = __shfl_xor_sync(FULLM, cmp, 1);
            if (c1 > cmp) cmp = c1;
            if (lane == 0) wmax_sh[w] = cmp;           // ph = 42&1 = 0
            if (lane < 2) out[(DECL - 1) * NV + row] = lgv;
        }
        if (w == 15) {
            ull v;
            for (;;) {
                v = (lane < 14) ? wmax_sh[lane] : 0ull;
                int ok = (lane < 14) ? ((int)(v & 0xffu) == 42) : 1;
                if (__all_sync(FULLM, ok)) break;
            }
            if (lane >= 14) v = 0ull;
#pragma unroll
            for (int o = 1; o < 32; o <<= 1) {
                ull ot = __shfl_xor_sync(FULLM, v, o);
                if (ot > v) v = ot;
            }
            if (lane == 0)
                out[NV * DECL + (DECL - 1)] = (float)(255 - (int)((v >> 8) & 0xffu));
        }
        __syncthreads();
        if (tid < 64) g_flag[tid] = 0;                 // reset for next graph replay
    }
    cluster_bar();
    (void)out_size; (void)ug;
}

// host-side fork/join resources (created once, on the uncaptured correctness call)
struct HxCtx {
    cudaStream_t s2;
    cudaEvent_t  eF, eJ;
    HxCtx() {
        cudaStreamCreateWithFlags(&s2, cudaStreamNonBlocking);
        cudaEventCreateWithFlags(&eF, cudaEventDisableTiming);
        cudaEventCreateWithFlags(&eJ, cudaEventDisableTiming);
    }
};
static HxCtx& hx_ctx() { static HxCtx c; return c; }

extern "C" void kernel_launch(void* const* d_in, const int* in_sizes, int n_in,
                              void* d_out, int out_size) {
    (void)in_sizes; (void)n_in;
    const int*   data     = (const int*)  d_in[0];
    const int*   data_c   = (const int*)  d_in[1];
    const int*   target_c = (const int*)  d_in[2];
    const float* cond_emb = (const float*)d_in[3];
    const float* enc_emb  = (const float*)d_in[4];
    const float* enc_Wih  = (const float*)d_in[5];
    const float* enc_Whh  = (const float*)d_in[6];
    const float* enc_bih  = (const float*)d_in[7];
    const float* enc_bhh  = (const float*)d_in[8];
    const float* hmu_W    = (const float*)d_in[9];
    const float* hmu_b    = (const float*)d_in[10];
    const float* cmu_W    = (const float*)d_in[11];
    const float* cmu_b    = (const float*)d_in[12];
    const float* fc1_W    = (const float*)d_in[13];
    const float* fc1_b    = (const float*)d_in[14];
    const float* fc2_W    = (const float*)d_in[15];
    const float* fc2_b    = (const float*)d_in[16];
    const float* dec_emb  = (const float*)d_in[17];
    const float* dec_Wih  = (const float*)d_in[18];
    const float* dec_Whh  = (const float*)d_in[19];
    const float* dec_bih  = (const float*)d_in[20];
    const float* dec_bhh  = (const float*)d_in[21];
    const float* out_W    = (const float*)d_in[22];
    const float* out_b    = (const float*)d_in[23];

    HxCtx& c = hx_ctx();

    cudaEventRecord(c.eF, 0);
    cudaStreamWaitEvent(c.s2, c.eF, 0);
    table_kernel<<<64, 256, 0, c.s2>>>(data, enc_Wih, enc_bih, enc_bhh, enc_emb,
                                       dec_Wih, dec_bih, dec_bhh, dec_emb);
    cudaEventRecord(c.eJ, c.s2);

    cudaFuncSetAttribute(vae_kernel, cudaFuncAttributeMaxDynamicSharedMemorySize, SMEM_BYTES);
    vae_kernel<<<CS, TPB, SMEM_BYTES>>>(data_c, target_c, cond_emb,
                                        enc_Whh,
                                        hmu_W, hmu_b, cmu_W, cmu_b,
                                        fc1_W, fc1_b, fc2_W, fc2_b,
                                        dec_Whh,
                                        out_W, out_b,
                                        (float*)d_out, out_size);
    cudaStreamWaitEvent(0, c.eJ, 0);
}

// round 15
// speedup vs baseline: 1.1085x; 1.1085x over previous
#include <cuda_runtime.h>
#include <math.h>
#include <stdint.h>

#define CS   8
#define TPB  512
#define HID  256
#define ENCL 16
#define DECL 25
#define NV   28

typedef unsigned long long ull;
#define FULLM 0xffffffffu

// projection tables, layout [t][unit 0..255][gate 0..3]
__device__ float g_pre[ENCL * 1024];
__device__ float g_tab[NV * 1024];
__device__ int   g_flag[64];         // [0..31] enc CTA done, [32..63] dec CTA done

// ---------------- smem layout (float offsets) ----------------
#define O_H3B   0               // 3 x 256 h ring
#define O_CF    768             // cfull [256]
#define O_PRE   1024            // [16][32 units][4 gates] = 2048
#define O_TAB   3072            // [28][32][4] = 3584
#define O_CATH  6656            // [40]
#define O_CATC  6696            // [40]
#define O_CNEW  6736            // [32]
#define O_WMAX  6768            // 2 phases x 16 ull = 64 floats
#define SMEM_FLOATS 6832
#define SMEM_BYTES  (SMEM_FLOATS * 4)

// ---------------- PTX helpers ----------------
__device__ __forceinline__ uint32_t smem_u32(const void* p) {
    uint32_t a;
    asm("{ .reg .u64 t; cvta.to.shared.u64 t, %1; cvt.u32.u64 %0, t; }" : "=r"(a) : "l"(p));
    return a;
}
__device__ __forceinline__ uint32_t mapa_u32(uint32_t a, uint32_t rank) {
    uint32_t r;
    asm("mapa.shared::cluster.u32 %0, %1, %2;" : "=r"(r) : "r"(a), "r"(rank));
    return r;
}
__device__ __forceinline__ void st_cluster_b64(uint32_t addr, ull v) {
    asm volatile("st.shared::cluster.b64 [%0], %1;" :: "r"(addr), "l"(v) : "memory");
}
__device__ __forceinline__ void cluster_bar() {
    asm volatile("barrier.cluster.arrive.aligned;" ::: "memory");
    asm volatile("barrier.cluster.wait.aligned;" ::: "memory");
}
__device__ __forceinline__ int ld_acq_gpu(const int* p) {
    int v;
    asm volatile("ld.acquire.gpu.global.s32 %0, [%1];" : "=r"(v) : "l"(p) : "memory");
    return v;
}
__device__ __forceinline__ void st_rel_gpu(int* p, int v) {
    asm volatile("st.release.gpu.global.s32 [%0], %1;" :: "l"(p), "r"(v) : "memory");
}
__device__ __forceinline__ void ffma2(ull &acc, ull a, ull b) {
    asm("fma.rn.f32x2 %0, %1, %2, %0;" : "+l"(acc) : "l"(a), "l"(b));
}
__device__ __forceinline__ float ups(ull a) {
    float lo, hi;
    asm("mov.b64 {%0,%1}, %2;" : "=f"(lo), "=f"(hi) : "l"(a));
    return lo + hi;
}
__device__ __forceinline__ ull pack2(float lo, float hi) {
    ull r;
    asm("mov.b64 %0, {%1,%2};" : "=l"(r) : "f"(lo), "f"(hi));
    return r;
}
__device__ __forceinline__ float sigf(float x) { return __fdividef(1.f, 1.f + __expf(-x)); }
__device__ __forceinline__ float tanhfast(float x) {
    float t = __expf(-2.f * fabsf(x));
    return copysignf(__fdividef(1.f - t, 1.f + t), x);
}
__device__ __forceinline__ float red32(float s) {
#pragma unroll
    for (int o = 16; o > 0; o >>= 1) s += __shfl_xor_sync(FULLM, s, o);
    return s;
}
__device__ __forceinline__ float dot8(float4 a0, float4 a1, float4 b0, float4 b1) {
    return a0.x*b0.x + a0.y*b0.y + a0.z*b0.z + a0.w*b0.w
         + a1.x*b1.x + a1.y*b1.y + a1.z*b1.z + a1.w*b1.w;
}
__device__ __forceinline__ void pf_l2(const void* p) {
    asm volatile("prefetch.global.L2 [%0];" :: "l"(p));
}

// 8 gate-row weight chunks (lane's 8 h-elems) for this warp
__device__ __forceinline__ void load_w8(const float* W, int b, int w, int lane, ull wr[8][4]) {
#pragma unroll
    for (int r = 0; r < 8; r++) {
        int row = (r & 3) * HID + b * 32 + 2 * w + (r >> 2);
        const ulonglong2* p = (const ulonglong2*)(W + row * HID + 8 * lane);
        ulonglong2 v0 = p[0], v1 = p[1];
        wr[r][0] = v0.x; wr[r][1] = v0.y; wr[r][2] = v1.x; wr[r][3] = v1.y;
    }
}

// multi-acc butterfly: 8 partials/lane -> every lane holds total of acc (lane&7)
__device__ __forceinline__ float reduce8(float a0, float a1, float a2, float a3,
                                         float a4, float a5, float a6, float a7, int lane) {
    a0 += __shfl_xor_sync(FULLM, a0, 16); a1 += __shfl_xor_sync(FULLM, a1, 16);
    a2 += __shfl_xor_sync(FULLM, a2, 16); a3 += __shfl_xor_sync(FULLM, a3, 16);
    a4 += __shfl_xor_sync(FULLM, a4, 16); a5 += __shfl_xor_sync(FULLM, a5, 16);
    a6 += __shfl_xor_sync(FULLM, a6, 16); a7 += __shfl_xor_sync(FULLM, a7, 16);
    a0 += __shfl_xor_sync(FULLM, a0, 8);  a1 += __shfl_xor_sync(FULLM, a1, 8);
    a2 += __shfl_xor_sync(FULLM, a2, 8);  a3 += __shfl_xor_sync(FULLM, a3, 8);
    a4 += __shfl_xor_sync(FULLM, a4, 8);  a5 += __shfl_xor_sync(FULLM, a5, 8);
    a6 += __shfl_xor_sync(FULLM, a6, 8);  a7 += __shfl_xor_sync(FULLM, a7, 8);
    bool b2 = (lane >> 2) & 1;
    float s0 = b2 ? a0 : a4, s1 = b2 ? a1 : a5, s2 = b2 ? a2 : a6, s3 = b2 ? a3 : a7;
    float r0 = __shfl_xor_sync(FULLM, s0, 4), r1 = __shfl_xor_sync(FULLM, s1, 4);
    float r2 = __shfl_xor_sync(FULLM, s2, 4), r3 = __shfl_xor_sync(FULLM, s3, 4);
    float k0 = (b2 ? a4 : a0) + r0, k1 = (b2 ? a5 : a1) + r1;
    float k2 = (b2 ? a6 : a2) + r2, k3 = (b2 ? a7 : a3) + r3;
    bool b1 = (lane >> 1) & 1;
    float t0 = b1 ? k0 : k2, t1 = b1 ? k1 : k3;
    float u0 = __shfl_xor_sync(FULLM, t0, 2), u1 = __shfl_xor_sync(FULLM, t1, 2);
    float m0 = (b1 ? k2 : k0) + u0, m1 = (b1 ? k3 : k1) + u1;
    bool b0 = lane & 1;
    float sv = b0 ? m0 : m1;
    float rv = __shfl_xor_sync(FULLM, sv, 1);
    return (b0 ? m1 : m0) + rv;
}
// 2-acc reduce: every lane gets total of acc (lane&1)
__device__ __forceinline__ float reduce2(float l0, float l1, int lane) {
    l0 += __shfl_xor_sync(FULLM, l0, 16); l1 += __shfl_xor_sync(FULLM, l1, 16);
    l0 += __shfl_xor_sync(FULLM, l0, 8);  l1 += __shfl_xor_sync(FULLM, l1, 8);
    l0 += __shfl_xor_sync(FULLM, l0, 4);  l1 += __shfl_xor_sync(FULLM, l1, 4);
    l0 += __shfl_xor_sync(FULLM, l0, 2);  l1 += __shfl_xor_sync(FULLM, l1, 2);
    bool b0 = lane & 1;
    float s = b0 ? l0 : l1;
    float r = __shfl_xor_sync(FULLM, s, 1);
    return (b0 ? l1 : l0) + r;
}

// ================= kernel 1: tables (64 CTAs; enc/dec halves in PARALLEL) =================
__global__ void __launch_bounds__(256) table_kernel(
    const int* data,
    const float* enc_Wih, const float* enc_bih, const float* enc_bhh, const float* enc_emb,
    const float* dec_Wih, const float* dec_bih, const float* dec_bhh, const float* dec_emb)
{
    __shared__ __align__(16) float xs[NV * HID];
    const int tid  = threadIdx.x;
    const int w    = tid >> 5;
    const int lane = tid & 31;
    const int g    = blockIdx.x;

    if (g < 32) {
        for (int i = tid; i < ENCL * 64; i += 256) {
            int t = i >> 6, c4 = i & 63;
            ((float4*)xs)[i] = ((const float4*)(enc_emb + data[t] * HID))[c4];
        }
        __syncthreads();
        int Rb = g * 32 + w * 4;
        float4 aw[4][2]; float bias[4];
#pragma unroll
        for (int r = 0; r < 4; r++) {
            const float4* p = (const float4*)(enc_Wih + (Rb + r) * HID);
            aw[r][0] = p[lane * 2]; aw[r][1] = p[lane * 2 + 1];
            bias[r] = enc_bih[Rb + r] + enc_bhh[Rb + r];
        }
#pragma unroll 1
        for (int t = 0; t < ENCL; t++) {
            const float4* xv = (const float4*)(xs + t * HID) + lane * 2;
            float4 x0 = xv[0], x1 = xv[1];
#pragma unroll
            for (int r = 0; r < 4; r++) {
                float s = red32(dot8(aw[r][0], aw[r][1], x0, x1));
                if (lane == 0) {
                    int R = Rb + r;
                    g_pre[t * 1024 + (R & 255) * 4 + (R >> 8)] = s + bias[r];
                }
            }
        }
        __syncthreads();
        if (tid == 0) st_rel_gpu(&g_flag[g], 1);
    } else {
        for (int i = tid; i < NV * 64; i += 256) {
            int tk = i >> 6, c4 = i & 63;
            float4 v = ((const float4*)(dec_emb + tk * HID))[c4];
            v.x = fmaxf(v.x, 0.f); v.y = fmaxf(v.y, 0.f);
            v.z = fmaxf(v.z, 0.f); v.w = fmaxf(v.w, 0.f);
            ((float4*)xs)[i] = v;
        }
        __syncthreads();
        int Rb = (g - 32) * 32 + w * 4;
        float4 aw[4][2]; float bias[4];
#pragma unroll
        for (int r = 0; r < 4; r++) {
            const float4* p = (const float4*)(dec_Wih + (Rb + r) * HID);
            aw[r][0] = p[lane * 2]; aw[r][1] = p[lane * 2 + 1];
            bias[r] = dec_bih[Rb + r] + dec_bhh[Rb + r];
        }
#pragma unroll 1
        for (int tk = 0; tk < NV; tk++) {
            const float4* xv = (const float4*)(xs + tk * HID) + lane * 2;
            float4 x0 = xv[0], x1 = xv[1];
#pragma unroll
            for (int r = 0; r < 4; r++) {
                float s = red32(dot8(aw[r][0], aw[r][1], x0, x1));
                if (lane == 0) {
                    int R = Rb + r;
                    g_tab[tk * 1024 + (R & 255) * 4 + (R >> 8)] = s + bias[r];
                }
            }
        }
        __syncthreads();
        if (tid == 0) st_rel_gpu(&g_flag[g], 1);
    }
}

// ================= kernel 2: lean-crossbar LSTM (R12 body, slice-local flag waits) =================
__global__ void __launch_bounds__(TPB, 1) __cluster_dims__(CS, 1, 1) vae_kernel(
    const int* data_c, const int* target_c, const float* cond_emb,
    const float* enc_Whh,
    const float* hmu_W, const float* hmu_b, const float* cmu_W, const float* cmu_b,
    const float* fc1_W, const float* fc1_b, const float* fc2_W, const float* fc2_b,
    const float* dec_Whh,
    const float* out_W, const float* out_b,
    float* out, int out_size)
{
    extern __shared__ __align__(16) float sm[];
    float* h3b    = sm + O_H3B;
    float* cfull  = sm + O_CF;
    float* pre_sh = sm + O_PRE;
    float* tab_sh = sm + O_TAB;
    float* cat_h  = sm + O_CATH;
    float* cat_c  = sm + O_CATC;
    float* cnew_sh= sm + O_CNEW;
    volatile ull* wmax_sh = (volatile ull*)(sm + O_WMAX);

    const int tid  = threadIdx.x;
    const int w    = tid >> 5;
    const int lane = tid & 31;
    const int b    = blockIdx.x;
    const int uu   = (lane >> 2) & 1;

    const uint32_t base   = smem_u32(sm);
    const uint32_t myrmap = mapa_u32(base, (uint32_t)(lane & 7));

    // encoder recurrent weights (cold DRAM, overlaps table kernel's work)
    ull wr[8][4];
    load_w8(enc_Whh, b, w, lane, wr);

    // L2 prefetch serial-path weights
    for (int i = tid; i < 1024; i += TPB) {
        int gi = i >> 8, off = i & 255;
        pf_l2((const char*)(dec_Whh + (gi * 256 + b * 32) * HID) + off * 128);
    }
    for (int i = tid; i < 256; i += TPB) {
        pf_l2((const char*)hmu_W + i * 128);
        pf_l2((const char*)cmu_W + i * 128);
    }
    for (int i = tid; i < 320; i += TPB) {
        pf_l2((const char*)fc1_W + i * 128);
        pf_l2((const char*)fc2_W + i * 128);
    }
    for (int i = tid; i < 224; i += TPB)
        pf_l2((const char*)out_W + i * 128);

    // ---- h0 (slot 0) + c0 ----
    const int dcid = data_c[0], tcid = target_c[0];
    if (tid < HID) {
        float v = (tid >= HID - 8) ? cond_emb[dcid * 8 + (tid - (HID - 8))] : 0.f;
        h3b[tid] = v;
    }
    int ug = b * 32 + 2 * w + uu;
    float creg = (ug >= HID - 8) ? cond_emb[dcid * 8 + (ug - (HID - 8))] : 0.f;

    // wait ONLY for the 4 enc-table CTAs covering this CTA's 128 gate rows:
    // enc table CTA g covers rows [g*32, g*32+32); we need rows q*256 + b*32 + j
    // => g in { b, b+8, b+16, b+24 }
    if (tid < 4) while (ld_acq_gpu(&g_flag[b + 8 * tid]) == 0) { }
    __syncthreads();
    for (int i = tid; i < ENCL * 32; i += TPB)
        ((float4*)pre_sh)[i] = ((const float4*)g_pre)[(i >> 5) * 256 + b * 32 + (i & 31)];

    __syncthreads();
    cluster_bar();

    // ================= encoder: n = 0..15 =================
#pragma unroll 1
    for (int n = 0; n < ENCL; n++) {
        int slot = n % 3, slot2 = (n + 1) % 3;
        const ulonglong2* hp = (const ulonglong2*)(h3b + slot * HID);
        ulonglong2 X = hp[lane * 2], Y = hp[lane * 2 + 1];
        float a[8];
#pragma unroll
        for (int r = 0; r < 8; r++) {
            ull ac = 0ull;
            ffma2(ac, wr[r][0], X.x); ffma2(ac, wr[r][1], X.y);
            ffma2(ac, wr[r][2], Y.x); ffma2(ac, wr[r][3], Y.y);
            a[r] = ups(ac);
        }
        float tot = reduce8(a[0], a[1], a[2], a[3], a[4], a[5], a[6], a[7], lane);
        int gb = lane & 28;
        float g0 = __shfl_sync(FULLM, tot, gb);
        float g1 = __shfl_sync(FULLM, tot, gb | 1);
        float g2 = __shfl_sync(FULLM, tot, gb | 2);
        float g3 = __shfl_sync(FULLM, tot, gb | 3);
        float4 pr = *(const float4*)(pre_sh + n * 128 + (2 * w + uu) * 4);
        float gi = g0 + pr.x, gf = g1 + pr.y, gg = g2 + pr.z, go = g3 + pr.w;
        float c = sigf(gf) * creg + sigf(gi) * tanhfast(gg);
        float h = sigf(go) * tanhfast(c);
        creg = c;
        float hA = __shfl_sync(FULLM, h, 0);
        float hB = __shfl_sync(FULLM, h, 4);
        if (lane < 8) {                               // 8 ranks in ONE warp instruction
            ull hp2 = pack2(hA, hB);
            uint32_t off = (uint32_t)((slot2 * HID + b * 32 + 2 * w) * 4);
            st_cluster_b64(myrmap + off, hp2);
        }
        if (n == ENCL - 1) {
            float cA = __shfl_sync(FULLM, c, 0);
            float cB = __shfl_sync(FULLM, c, 4);
            if (lane < 8) {
                ull cp = pack2(cA, cB);
                uint32_t co = (uint32_t)((O_CF + b * 32 + 2 * w) * 4);
                st_cluster_b64(myrmap + co, cp);
            }
        }
        cluster_bar();
    }

    // ================= latent heads + decoder init (redundant per CTA) =================
    {
        const float4* hv = (const float4*)(h3b + HID) + lane * 2;
        float4 h0v = hv[0], h1v = hv[1];
        const float4* cv = (const float4*)cfull + lane * 2;
        float4 c0v = cv[0], c1v = cv[1];
#pragma unroll
        for (int half = 0; half < 2; half++) {
            int rr = w + half * 16;
            const float4* pp = (const float4*)(hmu_W + rr * HID);
            float4 x0 = pp[lane * 2], x1 = pp[lane * 2 + 1];
            float s = red32(dot8(x0, x1, h0v, h1v));
            if (lane == 0) cat_h[rr] = s + hmu_b[rr];
            pp = (const float4*)(cmu_W + rr * HID);
            x0 = pp[lane * 2]; x1 = pp[lane * 2 + 1];
            s = red32(dot8(x0, x1, c0v, c1v));
            if (lane == 0) cat_c[rr] = s + cmu_b[rr];
        }
    }
    if (tid < 8) {
        float v = cond_emb[tcid * 8 + tid];
        cat_h[32 + tid] = v; cat_c[32 + tid] = v;
    }
    __syncthreads();
    float newv = 0.f;
    if (tid < HID) {
        float s = fc1_b[tid];
        const float* wrp = fc1_W + tid * 40;
#pragma unroll
        for (int k = 0; k < 40; k++) s += cat_h[k] * wrp[k];
        newv = s;
    }
    if (tid < 32) {
        int j = b * 32 + tid;
        float s = fc2_b[j];
        const float* wrp = fc2_W + j * 40;
#pragma unroll
        for (int k = 0; k < 40; k++) s += cat_c[k] * wrp[k];
        cnew_sh[tid] = s;
    }
    __syncthreads();
    if (tid < HID) h3b[2 * HID + tid] = newv;           // dh -> slot 2 (= h(17))
    creg = cnew_sh[2 * w + uu];

    // decoder token table (built long ago): wait only for this CTA's 4 source CTAs
    if (tid < 4) while (ld_acq_gpu(&g_flag[32 + b + 8 * tid]) == 0) { }
    __syncthreads();
    for (int i = tid; i < NV * 32; i += TPB)
        ((float4*)tab_sh)[i] = ((const float4*)g_tab)[(i >> 5) * 256 + b * 32 + (i & 31)];

    // decoder weights + out_W rows (2 per warp, w<14) into registers
    load_w8(dec_Whh, b, w, lane, wr);
    ull owr[2][4];
    {
        int lw = (w < 14) ? w : 0;
#pragma unroll
        for (int rr = 0; rr < 2; rr++) {
            const ulonglong2* p = (const ulonglong2*)(out_W + (2 * lw + rr) * HID + 8 * lane);
            ulonglong2 v0 = p[0], v1 = p[1];
            owr[rr][0] = v0.x; owr[rr][1] = v0.y; owr[rr][2] = v1.x; owr[rr][3] = v1.y;
        }
    }
    float obv = (w < 14) ? out_b[2 * w + (lane & 1)] : 0.f;
    __syncthreads();

    // ================= decoder: N = 17..41 =================
#pragma unroll 1
    for (int N = 17; N < 17 + DECL; N++) {
        int slot = N % 3, slot2 = (N + 1) % 3, ph = N & 1;
        const ulonglong2* hp = (const ulonglong2*)(h3b + slot * HID);
        ulonglong2 X = hp[lane * 2], Y = hp[lane * 2 + 1];

        float lgv = 0.f;
        if (w < 14 && N > 17) {
            ull la0 = 0ull, la1 = 0ull;
            ffma2(la0, owr[0][0], X.x); ffma2(la0, owr[0][1], X.y);
            ffma2(la0, owr[0][2], Y.x); ffma2(la0, owr[0][3], Y.y);
            ffma2(la1, owr[1][0], X.x); ffma2(la1, owr[1][1], X.y);
            ffma2(la1, owr[1][2], Y.x); ffma2(la1, owr[1][3], Y.y);
            lgv = reduce2(ups(la0), ups(la1), lane) + obv;
            uint32_t bits = __float_as_uint(lgv);
            uint32_t key = (bits & 0x80000000u) ? ~bits : (bits | 0x80000000u);
            int row = 2 * w + (lane & 1);
            ull cmp = ((ull)key << 8) | (ull)(255 - row);
            ull c1 = __shfl_xor_sync(FULLM, cmp, 1);
            if (c1 > cmp) cmp = c1;
            if (lane == 0) wmax_sh[ph * 16 + w] = cmp;
        }

        float a[8];
#pragma unroll
        for (int r = 0; r < 8; r++) {
            ull ac = 0ull;
            ffma2(ac, wr[r][0], X.x); ffma2(ac, wr[r][1], X.y);
            ffma2(ac, wr[r][2], Y.x); ffma2(ac, wr[r][3], Y.y);
            a[r] = ups(ac);
        }
        float tot = reduce8(a[0], a[1], a[2], a[3], a[4], a[5], a[6], a[7], lane);

        __syncthreads();

        int tok = 0;
        if (N > 17) {
            ull v = (lane < 14) ? wmax_sh[ph * 16 + lane] : 0ull;
#pragma unroll
            for (int o = 1; o < 32; o <<= 1) {
                ull ot = __shfl_xor_sync(FULLM, v, o);
                if (ot > v) v = ot;
            }
            tok = 255 - (int)(v & 0xffu);
            if (b == 0) {
                if (w < 14 && lane < 2) out[(N - 18) * NV + 2 * w + lane] = lgv;
                if (w == 15 && lane == 0) out[NV * DECL + (N - 18)] = (float)tok;
            }
        }

        int gb = lane & 28;
        float g0 = __shfl_sync(FULLM, tot, gb);
        float g1 = __shfl_sync(FULLM, tot, gb | 1);
        float g2 = __shfl_sync(FULLM, tot, gb | 2);
        float g3 = __shfl_sync(FULLM, tot, gb | 3);
        float4 pr = *(const float4*)(tab_sh + tok * 128 + (2 * w + uu) * 4);
        float gi = g0 + pr.x, gf = g1 + pr.y, gg = g2 + pr.z, go = g3 + pr.w;
        float c = sigf(gf) * creg + sigf(gi) * tanhfast(gg);
        float h = sigf(go) * tanhfast(c);
        creg = c;
        float hA = __shfl_sync(FULLM, h, 0);
        float hB = __shfl_sync(FULLM, h, 4);
        if (lane < 8) {
            ull hp2 = pack2(hA, hB);
            uint32_t off = (uint32_t)((slot2 * HID + b * 32 + 2 * w) * 4);
            st_cluster_b64(myrmap + off, hp2);
        }
        cluster_bar();
    }

    // ---- tail: logits/argmax of h(42) (slot 0) ----
    if (b == 0) {
        const ulonglong2* hp = (const ulonglong2*)h3b;
        ulonglong2 X = hp[lane * 2], Y = hp[lane * 2 + 1];
        float lgv = 0.f;
        if (w < 14) {
            ull la0 = 0ull, la1 = 0ull;
            ffma2(la0, owr[0][0], X.x); ffma2(la0, owr[0][1], X.y);
            ffma2(la0, owr[0][2], Y.x); ffma2(la0, owr[0][3], Y.y);
            ffma2(la1, owr[1][0], X.x); ffma2(la1, owr[1][1], X.y);
            ffma2(la1, owr[1][2], Y.x); ffma2(la1, owr[1][3], Y.y);
            lgv = reduce2(ups(la0), ups(la1), lane) + obv;
            uint32_t bits = __float_as_uint(lgv);
            uint32_t key = (bits & 0x80000000u) ? ~bits : (bits | 0x80000000u);
            int row = 2 * w + (lane & 1);
            ull cmp = ((ull)key << 8) | (ull)(255 - row);
            ull c1 = __shfl_xor_sync(FULLM, cmp, 1);
            if (c1 > cmp) cmp = c1;
            if (lane == 0) wmax_sh[w] = cmp;
            if (lane < 2) out[(DECL - 1) * NV + row] = lgv;
        }
        __syncthreads();
        if (w == 15) {
            ull v = (lane < 14) ? wmax_sh[lane] : 0ull;
#pragma unroll
            for (int o = 1; o < 32; o <<= 1) {
                ull ot = __shfl_xor_sync(FULLM, v, o);
                if (ot > v) v = ot;
            }
            if (lane == 0)
                out[NV * DECL + (DECL - 1)] = (float)(255 - (int)(v & 0xffu));
        }
        // reset flags for the next graph replay (replays serialize, so safe)
        if (tid < 64) g_flag[tid] = 0;
    }
    cluster_bar();
    (void)out_size; (void)ug;
}

// host-side fork/join resources (created once, on the uncaptured correctness call)
struct HxCtx {
    cudaStream_t s2;
    cudaEvent_t  eF, eJ;
    bool attr_set;
    HxCtx() : attr_set(false) {
        cudaStreamCreateWithFlags(&s2, cudaStreamNonBlocking);
        cudaEventCreateWithFlags(&eF, cudaEventDisableTiming);
        cudaEventCreateWithFlags(&eJ, cudaEventDisableTiming);
    }
};
static HxCtx& hx_ctx() { static HxCtx c; return c; }

extern "C" void kernel_launch(void* const* d_in, const int* in_sizes, int n_in,
                              void* d_out, int out_size) {
    (void)in_sizes; (void)n_in;
    const int*   data     = (const int*)  d_in[0];
    const int*   data_c   = (const int*)  d_in[1];
    const int*   target_c = (const int*)  d_in[2];
    const float* cond_emb = (const float*)d_in[3];
    const float* enc_emb  = (const float*)d_in[4];
    const float* enc_Wih  = (const float*)d_in[5];
    const float* enc_Whh  = (const float*)d_in[6];
    const float* enc_bih  = (const float*)d_in[7];
    const float* enc_bhh  = (const float*)d_in[8];
    const float* hmu_W    = (const float*)d_in[9];
    const float* hmu_b    = (const float*)d_in[10];
    const float* cmu_W    = (const float*)d_in[11];
    const float* cmu_b    = (const float*)d_in[12];
    const float* fc1_W    = (const float*)d_in[13];
    const float* fc1_b    = (const float*)d_in[14];
    const float* fc2_W    = (const float*)d_in[15];
    const float* fc2_b    = (const float*)d_in[16];
    const float* dec_emb  = (const float*)d_in[17];
    const float* dec_Wih  = (const float*)d_in[18];
    const float* dec_Whh  = (const float*)d_in[19];
    const float* dec_bih  = (const float*)d_in[20];
    const float* dec_bhh  = (const float*)d_in[21];
    const float* out_W    = (const float*)d_in[22];
    const float* out_b    = (const float*)d_in[23];

    HxCtx& c = hx_ctx();
    if (!c.attr_set) {
        cudaFuncSetAttribute(vae_kernel, cudaFuncAttributeMaxDynamicSharedMemorySize, SMEM_BYTES);
        c.attr_set = true;
    }

    // R12-proven order: table kernel FIRST on forked stream, vae second on stream 0
    cudaEventRecord(c.eF, 0);
    cudaStreamWaitEvent(c.s2, c.eF, 0);
    table_kernel<<<64, 256, 0, c.s2>>>(data, enc_Wih, enc_bih, enc_bhh, enc_emb,
                                       dec_Wih, dec_bih, dec_bhh, dec_emb);
    cudaEventRecord(c.eJ, c.s2);

    vae_kernel<<<CS, TPB, SMEM_BYTES>>>(data_c, target_c, cond_emb,
                                        enc_Whh,
                                        hmu_W, hmu_b, cmu_W, cmu_b,
                                        fc1_W, fc1_b, fc2_W, fc2_b,
                                        dec_Whh,
                                        out_W, out_b,
                                        (float*)d_out, out_size);
    cudaStreamWaitEvent(0, c.eJ, 0);
}

// round 16
// speedup vs baseline: 1.1137x; 1.0047x over previous
#include <cuda_runtime.h>
#include <math.h>
#include <stdint.h>

#define CS   8
#define TPB  512
#define HID  256
#define ENCL 16
#define DECL 25
#define NV   28

typedef unsigned long long ull;
#define FULLM 0xffffffffu

// projection tables, layout [t][unit 0..255][gate 0..3]
__device__ float g_pre[ENCL * 1024];
__device__ float g_tab[NV * 1024];
__device__ int   g_flag[64];         // [0..31] enc CTA done, [32..63] dec CTA done

// ---------------- smem layout (float offsets) ----------------
#define O_H3B   0               // 3 x 256 h ring
#define O_CF    768             // cfull [256]
#define O_PRE   1024            // [16][32 units][4 gates] = 2048
#define O_TAB   3072            // [28][32][4] = 3584
#define O_CATH  6656            // [40]
#define O_CATC  6696            // [40]
#define O_CNEW  6736            // [32]
#define O_WMAX  6768            // 2 phases x 16 ull = 64 floats
#define SMEM_FLOATS 6832
#define SMEM_BYTES  (SMEM_FLOATS * 4)

// ---------------- PTX helpers ----------------
__device__ __forceinline__ uint32_t smem_u32(const void* p) {
    uint32_t a;
    asm("{ .reg .u64 t; cvta.to.shared.u64 t, %1; cvt.u32.u64 %0, t; }" : "=r"(a) : "l"(p));
    return a;
}
__device__ __forceinline__ uint32_t mapa_u32(uint32_t a, uint32_t rank) {
    uint32_t r;
    asm("mapa.shared::cluster.u32 %0, %1, %2;" : "=r"(r) : "r"(a), "r"(rank));
    return r;
}
__device__ __forceinline__ void st_cluster_b64(uint32_t addr, ull v) {
    asm volatile("st.shared::cluster.b64 [%0], %1;" :: "r"(addr), "l"(v) : "memory");
}
__device__ __forceinline__ void cluster_bar() {
    asm volatile("barrier.cluster.arrive.aligned;" ::: "memory");
    asm volatile("barrier.cluster.wait.aligned;" ::: "memory");
}
__device__ __forceinline__ void cluster_arrive() {
    asm volatile("barrier.cluster.arrive.aligned;" ::: "memory");
}
__device__ __forceinline__ void cluster_wait() {
    asm volatile("barrier.cluster.wait.aligned;" ::: "memory");
}
__device__ __forceinline__ int ld_acq_gpu(const int* p) {
    int v;
    asm volatile("ld.acquire.gpu.global.s32 %0, [%1];" : "=r"(v) : "l"(p) : "memory");
    return v;
}
__device__ __forceinline__ void st_rel_gpu(int* p, int v) {
    asm volatile("st.release.gpu.global.s32 [%0], %1;" :: "l"(p), "r"(v) : "memory");
}
__device__ __forceinline__ void ffma2(ull &acc, ull a, ull b) {
    asm("fma.rn.f32x2 %0, %1, %2, %0;" : "+l"(acc) : "l"(a), "l"(b));
}
__device__ __forceinline__ float ups(ull a) {
    float lo, hi;
    asm("mov.b64 {%0,%1}, %2;" : "=f"(lo), "=f"(hi) : "l"(a));
    return lo + hi;
}
__device__ __forceinline__ ull pack2(float lo, float hi) {
    ull r;
    asm("mov.b64 %0, {%1,%2};" : "=l"(r) : "f"(lo), "f"(hi));
    return r;
}
__device__ __forceinline__ float sigf(float x) { return __fdividef(1.f, 1.f + __expf(-x)); }
__device__ __forceinline__ float tanhfast(float x) {
    float t = __expf(-2.f * fabsf(x));
    return copysignf(__fdividef(1.f - t, 1.f + t), x);
}
__device__ __forceinline__ float red32(float s) {
#pragma unroll
    for (int o = 16; o > 0; o >>= 1) s += __shfl_xor_sync(FULLM, s, o);
    return s;
}
__device__ __forceinline__ float dot8(float4 a0, float4 a1, float4 b0, float4 b1) {
    return a0.x*b0.x + a0.y*b0.y + a0.z*b0.z + a0.w*b0.w
         + a1.x*b1.x + a1.y*b1.y + a1.z*b1.z + a1.w*b1.w;
}
__device__ __forceinline__ void pf_l2(const void* p) {
    asm volatile("prefetch.global.L2 [%0];" :: "l"(p));
}

// 8 gate-row weight chunks (lane's 8 h-elems) for this warp
__device__ __forceinline__ void load_w8(const float* W, int b, int w, int lane, ull wr[8][4]) {
#pragma unroll
    for (int r = 0; r < 8; r++) {
        int row = (r & 3) * HID + b * 32 + 2 * w + (r >> 2);
        const ulonglong2* p = (const ulonglong2*)(W + row * HID + 8 * lane);
        ulonglong2 v0 = p[0], v1 = p[1];
        wr[r][0] = v0.x; wr[r][1] = v0.y; wr[r][2] = v1.x; wr[r][3] = v1.y;
    }
}

// multi-acc butterfly: 8 partials/lane -> every lane holds total of acc (lane&7)
__device__ __forceinline__ float reduce8(float a0, float a1, float a2, float a3,
                                         float a4, float a5, float a6, float a7, int lane) {
    a0 += __shfl_xor_sync(FULLM, a0, 16); a1 += __shfl_xor_sync(FULLM, a1, 16);
    a2 += __shfl_xor_sync(FULLM, a2, 16); a3 += __shfl_xor_sync(FULLM, a3, 16);
    a4 += __shfl_xor_sync(FULLM, a4, 16); a5 += __shfl_xor_sync(FULLM, a5, 16);
    a6 += __shfl_xor_sync(FULLM, a6, 16); a7 += __shfl_xor_sync(FULLM, a7, 16);
    a0 += __shfl_xor_sync(FULLM, a0, 8);  a1 += __shfl_xor_sync(FULLM, a1, 8);
    a2 += __shfl_xor_sync(FULLM, a2, 8);  a3 += __shfl_xor_sync(FULLM, a3, 8);
    a4 += __shfl_xor_sync(FULLM, a4, 8);  a5 += __shfl_xor_sync(FULLM, a5, 8);
    a6 += __shfl_xor_sync(FULLM, a6, 8);  a7 += __shfl_xor_sync(FULLM, a7, 8);
    bool b2 = (lane >> 2) & 1;
    float s0 = b2 ? a0 : a4, s1 = b2 ? a1 : a5, s2 = b2 ? a2 : a6, s3 = b2 ? a3 : a7;
    float r0 = __shfl_xor_sync(FULLM, s0, 4), r1 = __shfl_xor_sync(FULLM, s1, 4);
    float r2 = __shfl_xor_sync(FULLM, s2, 4), r3 = __shfl_xor_sync(FULLM, s3, 4);
    float k0 = (b2 ? a4 : a0) + r0, k1 = (b2 ? a5 : a1) + r1;
    float k2 = (b2 ? a6 : a2) + r2, k3 = (b2 ? a7 : a3) + r3;
    bool b1 = (lane >> 1) & 1;
    float t0 = b1 ? k0 : k2, t1 = b1 ? k1 : k3;
    float u0 = __shfl_xor_sync(FULLM, t0, 2), u1 = __shfl_xor_sync(FULLM, t1, 2);
    float m0 = (b1 ? k2 : k0) + u0, m1 = (b1 ? k3 : k1) + u1;
    bool b0 = lane & 1;
    float sv = b0 ? m0 : m1;
    float rv = __shfl_xor_sync(FULLM, sv, 1);
    return (b0 ? m1 : m0) + rv;
}
// 2-acc reduce: every lane gets total of acc (lane&1)
__device__ __forceinline__ float reduce2(float l0, float l1, int lane) {
    l0 += __shfl_xor_sync(FULLM, l0, 16); l1 += __shfl_xor_sync(FULLM, l1, 16);
    l0 += __shfl_xor_sync(FULLM, l0, 8);  l1 += __shfl_xor_sync(FULLM, l1, 8);
    l0 += __shfl_xor_sync(FULLM, l0, 4);  l1 += __shfl_xor_sync(FULLM, l1, 4);
    l0 += __shfl_xor_sync(FULLM, l0, 2);  l1 += __shfl_xor_sync(FULLM, l1, 2);
    bool b0 = lane & 1;
    float s = b0 ? l0 : l1;
    float r = __shfl_xor_sync(FULLM, s, 1);
    return (b0 ? l1 : l0) + r;
}

// ================= kernel 1: tables (64 CTAs; enc/dec halves in PARALLEL) =================
__global__ void __launch_bounds__(256) table_kernel(
    const int* data,
    const float* enc_Wih, const float* enc_bih, const float* enc_bhh, const float* enc_emb,
    const float* dec_Wih, const float* dec_bih, const float* dec_bhh, const float* dec_emb)
{
    __shared__ __align__(16) float xs[NV * HID];
    const int tid  = threadIdx.x;
    const int w    = tid >> 5;
    const int lane = tid & 31;
    const int g    = blockIdx.x;

    if (g < 32) {
        for (int i = tid; i < ENCL * 64; i += 256) {
            int t = i >> 6, c4 = i & 63;
            ((float4*)xs)[i] = ((const float4*)(enc_emb + data[t] * HID))[c4];
        }
        __syncthreads();
        int Rb = g * 32 + w * 4;
        float4 aw[4][2]; float bias[4];
#pragma unroll
        for (int r = 0; r < 4; r++) {
            const float4* p = (const float4*)(enc_Wih + (Rb + r) * HID);
            aw[r][0] = p[lane * 2]; aw[r][1] = p[lane * 2 + 1];
            bias[r] = enc_bih[Rb + r] + enc_bhh[Rb + r];
        }
#pragma unroll 1
        for (int t = 0; t < ENCL; t++) {
            const float4* xv = (const float4*)(xs + t * HID) + lane * 2;
            float4 x0 = xv[0], x1 = xv[1];
#pragma unroll
            for (int r = 0; r < 4; r++) {
                float s = red32(dot8(aw[r][0], aw[r][1], x0, x1));
                if (lane == 0) {
                    int R = Rb + r;
                    g_pre[t * 1024 + (R & 255) * 4 + (R >> 8)] = s + bias[r];
                }
            }
        }
        __syncthreads();
        if (tid == 0) st_rel_gpu(&g_flag[g], 1);
    } else {
        for (int i = tid; i < NV * 64; i += 256) {
            int tk = i >> 6, c4 = i & 63;
            float4 v = ((const float4*)(dec_emb + tk * HID))[c4];
            v.x = fmaxf(v.x, 0.f); v.y = fmaxf(v.y, 0.f);
            v.z = fmaxf(v.z, 0.f); v.w = fmaxf(v.w, 0.f);
            ((float4*)xs)[i] = v;
        }
        __syncthreads();
        int Rb = (g - 32) * 32 + w * 4;
        float4 aw[4][2]; float bias[4];
#pragma unroll
        for (int r = 0; r < 4; r++) {
            const float4* p = (const float4*)(dec_Wih + (Rb + r) * HID);
            aw[r][0] = p[lane * 2]; aw[r][1] = p[lane * 2 + 1];
            bias[r] = dec_bih[Rb + r] + dec_bhh[Rb + r];
        }
#pragma unroll 1
        for (int tk = 0; tk < NV; tk++) {
            const float4* xv = (const float4*)(xs + tk * HID) + lane * 2;
            float4 x0 = xv[0], x1 = xv[1];
#pragma unroll
            for (int r = 0; r < 4; r++) {
                float s = red32(dot8(aw[r][0], aw[r][1], x0, x1));
                if (lane == 0) {
                    int R = Rb + r;
                    g_tab[tk * 1024 + (R & 255) * 4 + (R >> 8)] = s + bias[r];
                }
            }
        }
        __syncthreads();
        if (tid == 0) st_rel_gpu(&g_flag[g], 1);
    }
}

// ================= kernel 2: lean-crossbar LSTM, split arrive/wait =================
__global__ void __launch_bounds__(TPB, 1) __cluster_dims__(CS, 1, 1) vae_kernel(
    const int* data_c, const int* target_c, const float* cond_emb,
    const float* enc_Whh,
    const float* hmu_W, const float* hmu_b, const float* cmu_W, const float* cmu_b,
    const float* fc1_W, const float* fc1_b, const float* fc2_W, const float* fc2_b,
    const float* dec_Whh,
    const float* out_W, const float* out_b,
    float* out, int out_size)
{
    extern __shared__ __align__(16) float sm[];
    float* h3b    = sm + O_H3B;
    float* cfull  = sm + O_CF;
    float* pre_sh = sm + O_PRE;
    float* tab_sh = sm + O_TAB;
    float* cat_h  = sm + O_CATH;
    float* cat_c  = sm + O_CATC;
    float* cnew_sh= sm + O_CNEW;
    volatile ull* wmax_sh = (volatile ull*)(sm + O_WMAX);

    const int tid  = threadIdx.x;
    const int w    = tid >> 5;
    const int lane = tid & 31;
    const int b    = blockIdx.x;
    const int uu   = (lane >> 2) & 1;

    const uint32_t base   = smem_u32(sm);
    const uint32_t myrmap = mapa_u32(base, (uint32_t)(lane & 7));

    // encoder recurrent weights (cold DRAM, overlaps table kernel's work)
    ull wr[8][4];
    load_w8(enc_Whh, b, w, lane, wr);

    // L2 prefetch serial-path weights
    for (int i = tid; i < 1024; i += TPB) {
        int gi = i >> 8, off = i & 255;
        pf_l2((const char*)(dec_Whh + (gi * 256 + b * 32) * HID) + off * 128);
    }
    for (int i = tid; i < 256; i += TPB) {
        pf_l2((const char*)hmu_W + i * 128);
        pf_l2((const char*)cmu_W + i * 128);
    }
    for (int i = tid; i < 320; i += TPB) {
        pf_l2((const char*)fc1_W + i * 128);
        pf_l2((const char*)fc2_W + i * 128);
    }
    for (int i = tid; i < 224; i += TPB)
        pf_l2((const char*)out_W + i * 128);

    // ---- h0 (slot 0) + c0 ----
    const int dcid = data_c[0], tcid = target_c[0];
    if (tid < HID) {
        float v = (tid >= HID - 8) ? cond_emb[dcid * 8 + (tid - (HID - 8))] : 0.f;
        h3b[tid] = v;
    }
    int ug = b * 32 + 2 * w + uu;
    float creg = (ug >= HID - 8) ? cond_emb[dcid * 8 + (ug - (HID - 8))] : 0.f;

    // wait ONLY for the 4 enc-table CTAs covering this CTA's 128 gate rows
    if (tid < 4) while (ld_acq_gpu(&g_flag[b + 8 * tid]) == 0) { }
    __syncthreads();
    for (int i = tid; i < ENCL * 32; i += TPB)
        ((float4*)pre_sh)[i] = ((const float4*)g_pre)[(i >> 5) * 256 + b * 32 + (i & 31)];

    __syncthreads();
    cluster_bar();

    // ================= encoder: n = 0..15 (split arrive/wait) =================
    // prefetch pr for step 0
    float4 pr = *(const float4*)(pre_sh + 0 * 128 + (2 * w + uu) * 4);
#pragma unroll 1
    for (int n = 0; n < ENCL; n++) {
        int slot = n % 3, slot2 = (n + 1) % 3;
        const ulonglong2* hp = (const ulonglong2*)(h3b + slot * HID);
        ulonglong2 X = hp[lane * 2], Y = hp[lane * 2 + 1];
        float a[8];
#pragma unroll
        for (int r = 0; r < 8; r++) {
            ull ac = 0ull;
            ffma2(ac, wr[r][0], X.x); ffma2(ac, wr[r][1], X.y);
            ffma2(ac, wr[r][2], Y.x); ffma2(ac, wr[r][3], Y.y);
            a[r] = ups(ac);
        }
        float tot = reduce8(a[0], a[1], a[2], a[3], a[4], a[5], a[6], a[7], lane);
        int gb = lane & 28;
        float g0 = __shfl_sync(FULLM, tot, gb);
        float g1 = __shfl_sync(FULLM, tot, gb | 1);
        float g2 = __shfl_sync(FULLM, tot, gb | 2);
        float g3 = __shfl_sync(FULLM, tot, gb | 3);
        float gi = g0 + pr.x, gf = g1 + pr.y, gg = g2 + pr.z, go = g3 + pr.w;
        float c = sigf(gf) * creg + sigf(gi) * tanhfast(gg);
        float h = sigf(go) * tanhfast(c);
        creg = c;
        float hA = __shfl_sync(FULLM, h, 0);
        float hB = __shfl_sync(FULLM, h, 4);
        if (lane < 8) {                               // 8 ranks in ONE warp instruction
            ull hp2 = pack2(hA, hB);
            uint32_t off = (uint32_t)((slot2 * HID + b * 32 + 2 * w) * 4);
            st_cluster_b64(myrmap + off, hp2);
        }
        if (n == ENCL - 1) {
            float cA = __shfl_sync(FULLM, c, 0);
            float cB = __shfl_sync(FULLM, c, 4);
            if (lane < 8) {
                ull cp = pack2(cA, cB);
                uint32_t co = (uint32_t)((O_CF + b * 32 + 2 * w) * 4);
                st_cluster_b64(myrmap + co, cp);
            }
        }
        cluster_arrive();
        // window: prefetch next step's pre row (own-CTA constant smem)
        if (n + 1 < ENCL)
            pr = *(const float4*)(pre_sh + (n + 1) * 128 + (2 * w + uu) * 4);
        cluster_wait();
    }

    // ================= latent heads + decoder init (redundant per CTA) =================
    {
        const float4* hv = (const float4*)(h3b + HID) + lane * 2;
        float4 h0v = hv[0], h1v = hv[1];
        const float4* cv = (const float4*)cfull + lane * 2;
        float4 c0v = cv[0], c1v = cv[1];
#pragma unroll
        for (int half = 0; half < 2; half++) {
            int rr = w + half * 16;
            const float4* pp = (const float4*)(hmu_W + rr * HID);
            float4 x0 = pp[lane * 2], x1 = pp[lane * 2 + 1];
            float s = red32(dot8(x0, x1, h0v, h1v));
            if (lane == 0) cat_h[rr] = s + hmu_b[rr];
            pp = (const float4*)(cmu_W + rr * HID);
            x0 = pp[lane * 2]; x1 = pp[lane * 2 + 1];
            s = red32(dot8(x0, x1, c0v, c1v));
            if (lane == 0) cat_c[rr] = s + cmu_b[rr];
        }
    }
    if (tid < 8) {
        float v = cond_emb[tcid * 8 + tid];
        cat_h[32 + tid] = v; cat_c[32 + tid] = v;
    }
    __syncthreads();
    float newv = 0.f;
    if (tid < HID) {
        float s = fc1_b[tid];
        const float* wrp = fc1_W + tid * 40;
#pragma unroll
        for (int k = 0; k < 40; k++) s += cat_h[k] * wrp[k];
        newv = s;
    }
    if (tid < 32) {
        int j = b * 32 + tid;
        float s = fc2_b[j];
        const float* wrp = fc2_W + j * 40;
#pragma unroll
        for (int k = 0; k < 40; k++) s += cat_c[k] * wrp[k];
        cnew_sh[tid] = s;
    }
    __syncthreads();
    if (tid < HID) h3b[2 * HID + tid] = newv;           // dh -> slot 2 (= h(17))
    creg = cnew_sh[2 * w + uu];

    // decoder token table: wait only for this CTA's 4 source CTAs
    if (tid < 4) while (ld_acq_gpu(&g_flag[32 + b + 8 * tid]) == 0) { }
    __syncthreads();
    for (int i = tid; i < NV * 32; i += TPB)
        ((float4*)tab_sh)[i] = ((const float4*)g_tab)[(i >> 5) * 256 + b * 32 + (i & 31)];

    // decoder weights + out_W rows (2 per warp, w<14) into registers
    load_w8(dec_Whh, b, w, lane, wr);
    ull owr[2][4];
    {
        int lw = (w < 14) ? w : 0;
#pragma unroll
        for (int rr = 0; rr < 2; rr++) {
            const ulonglong2* p = (const ulonglong2*)(out_W + (2 * lw + rr) * HID + 8 * lane);
            ulonglong2 v0 = p[0], v1 = p[1];
            owr[rr][0] = v0.x; owr[rr][1] = v0.y; owr[rr][2] = v1.x; owr[rr][3] = v1.y;
        }
    }
    float obv = (w < 14) ? out_b[2 * w + (lane & 1)] : 0.f;
    __syncthreads();

    // ================= decoder: N = 17..41 (split arrive/wait) =================
#pragma unroll 1
    for (int N = 17; N < 17 + DECL; N++) {
        int slot = N % 3, slot2 = (N + 1) % 3, ph = N & 1;
        const ulonglong2* hp = (const ulonglong2*)(h3b + slot * HID);
        ulonglong2 X = hp[lane * 2], Y = hp[lane * 2 + 1];

        float lgv = 0.f;
        if (w < 14 && N > 17) {
            ull la0 = 0ull, la1 = 0ull;
            ffma2(la0, owr[0][0], X.x); ffma2(la0, owr[0][1], X.y);
            ffma2(la0, owr[0][2], Y.x); ffma2(la0, owr[0][3], Y.y);
            ffma2(la1, owr[1][0], X.x); ffma2(la1, owr[1][1], X.y);
            ffma2(la1, owr[1][2], Y.x); ffma2(la1, owr[1][3], Y.y);
            lgv = reduce2(ups(la0), ups(la1), lane) + obv;
            uint32_t bits = __float_as_uint(lgv);
            uint32_t key = (bits & 0x80000000u) ? ~bits : (bits | 0x80000000u);
            int row = 2 * w + (lane & 1);
            ull cmp = ((ull)key << 8) | (ull)(255 - row);
            ull c1 = __shfl_xor_sync(FULLM, cmp, 1);
            if (c1 > cmp) cmp = c1;
            if (lane == 0) wmax_sh[ph * 16 + w] = cmp;
        }

        float a[8];
#pragma unroll
        for (int r = 0; r < 8; r++) {
            ull ac = 0ull;
            ffma2(ac, wr[r][0], X.x); ffma2(ac, wr[r][1], X.y);
            ffma2(ac, wr[r][2], Y.x); ffma2(ac, wr[r][3], Y.y);
            a[r] = ups(ac);
        }
        float tot = reduce8(a[0], a[1], a[2], a[3], a[4], a[5], a[6], a[7], lane);

        __syncthreads();

        int tok = 0;
        if (N > 17) {
            ull v = (lane < 14) ? wmax_sh[ph * 16 + lane] : 0ull;
#pragma unroll
            for (int o = 1; o < 32; o <<= 1) {
                ull ot = __shfl_xor_sync(FULLM, v, o);
                if (ot > v) v = ot;
            }
            tok = 255 - (int)(v & 0xffu);
        }

        int gb = lane & 28;
        float g0 = __shfl_sync(FULLM, tot, gb);
        float g1 = __shfl_sync(FULLM, tot, gb | 1);
        float g2 = __shfl_sync(FULLM, tot, gb | 2);
        float g3 = __shfl_sync(FULLM, tot, gb | 3);
        float4 prd = *(const float4*)(tab_sh + tok * 128 + (2 * w + uu) * 4);
        float gi = g0 + prd.x, gf = g1 + prd.y, gg = g2 + prd.z, go = g3 + prd.w;
        float c = sigf(gf) * creg + sigf(gi) * tanhfast(gg);
        float h = sigf(go) * tanhfast(c);
        creg = c;
        float hA = __shfl_sync(FULLM, h, 0);
        float hB = __shfl_sync(FULLM, h, 4);
        if (lane < 8) {
            ull hp2 = pack2(hA, hB);
            uint32_t off = (uint32_t)((slot2 * HID + b * 32 + 2 * w) * 4);
            st_cluster_b64(myrmap + off, hp2);
        }
        cluster_arrive();
        // window: rank-0 global output writes (off the protected smem path)
        if (b == 0 && N > 17) {
            if (w < 14 && lane < 2) out[(N - 18) * NV + 2 * w + lane] = lgv;
            if (w == 15 && lane == 0) out[NV * DECL + (N - 18)] = (float)tok;
        }
        cluster_wait();
    }

    // ---- tail: logits/argmax of h(42) (slot 0) ----
    if (b == 0) {
        const ulonglong2* hp = (const ulonglong2*)h3b;
        ulonglong2 X = hp[lane * 2], Y = hp[lane * 2 + 1];
        float lgv = 0.f;
        if (w < 14) {
            ull la0 = 0ull, la1 = 0ull;
            ffma2(la0, owr[0][0], X.x); ffma2(la0, owr[0][1], X.y);
            ffma2(la0, owr[0][2], Y.x); ffma2(la0, owr[0][3], Y.y);
            ffma2(la1, owr[1][0], X.x); ffma2(la1, owr[1][1], X.y);
            ffma2(la1, owr[1][2], Y.x); ffma2(la1, owr[1][3], Y.y);
            lgv = reduce2(ups(la0), ups(la1), lane) + obv;
            uint32_t bits = __float_as_uint(lgv);
            uint32_t key = (bits & 0x80000000u) ? ~bits : (bits | 0x80000000u);
            int row = 2 * w + (lane & 1);
            ull cmp = ((ull)key << 8) | (ull)(255 - row);
            ull c1 = __shfl_xor_sync(FULLM, cmp, 1);
            if (c1 > cmp) cmp = c1;
            if (lane == 0) wmax_sh[w] = cmp;
            if (lane < 2) out[(DECL - 1) * NV + row] = lgv;
        }
        __syncthreads();
        if (w == 15) {
            ull v = (lane < 14) ? wmax_sh[lane] : 0ull;
#pragma unroll
            for (int o = 1; o < 32; o <<= 1) {
                ull ot = __shfl_xor_sync(FULLM, v, o);
                if (ot > v) v = ot;
            }
            if (lane == 0)
                out[NV * DECL + (DECL - 1)] = (float)(255 - (int)(v & 0xffu));
        }
        // reset flags for the next graph replay (replays serialize, so safe)
        if (tid < 64) g_flag[tid] = 0;
    }
    cluster_bar();
    (void)out_size; (void)ug;
}

// host-side fork/join resources (created once, on the uncaptured correctness call)
struct HxCtx {
    cudaStream_t s2;
    cudaEvent_t  eF, eJ;
    bool attr_set;
    HxCtx() : attr_set(false) {
        cudaStreamCreateWithFlags(&s2, cudaStreamNonBlocking);
        cudaEventCreateWithFlags(&eF, cudaEventDisableTiming);
        cudaEventCreateWithFlags(&eJ, cudaEventDisableTiming);
    }
};
static HxCtx& hx_ctx() { static HxCtx c; return c; }

extern "C" void kernel_launch(void* const* d_in, const int* in_sizes, int n_in,
                              void* d_out, int out_size) {
    (void)in_sizes; (void)n_in;
    const int*   data     = (const int*)  d_in[0];
    const int*   data_c   = (const int*)  d_in[1];
    const int*   target_c = (const int*)  d_in[2];
    const float* cond_emb = (const float*)d_in[3];
    const float* enc_emb  = (const float*)d_in[4];
    const float* enc_Wih  = (const float*)d_in[5];
    const float* enc_Whh  = (const float*)d_in[6];
    const float* enc_bih  = (const float*)d_in[7];
    const float* enc_bhh  = (const float*)d_in[8];
    const float* hmu_W    = (const float*)d_in[9];
    const float* hmu_b    = (const float*)d_in[10];
    const float* cmu_W    = (const float*)d_in[11];
    const float* cmu_b    = (const float*)d_in[12];
    const float* fc1_W    = (const float*)d_in[13];
    const float* fc1_b    = (const float*)d_in[14];
    const float* fc2_W    = (const float*)d_in[15];
    const float* fc2_b    = (const float*)d_in[16];
    const float* dec_emb  = (const float*)d_in[17];
    const float* dec_Wih  = (const float*)d_in[18];
    const float* dec_Whh  = (const float*)d_in[19];
    const float* dec_bih  = (const float*)d_in[20];
    const float* dec_bhh  = (const float*)d_in[21];
    const float* out_W    = (const float*)d_in[22];
    const float* out_b    = (const float*)d_in[23];

    HxCtx& c = hx_ctx();
    if (!c.attr_set) {
        cudaFuncSetAttribute(vae_kernel, cudaFuncAttributeMaxDynamicSharedMemorySize, SMEM_BYTES);
        c.attr_set = true;
    }

    // R12-proven order: table kernel FIRST on forked stream, vae second on stream 0
    cudaEventRecord(c.eF, 0);
    cudaStreamWaitEvent(c.s2, c.eF, 0);
    table_kernel<<<64, 256, 0, c.s2>>>(data, enc_Wih, enc_bih, enc_bhh, enc_emb,
                                       dec_Wih, dec_bih, dec_bhh, dec_emb);
    cudaEventRecord(c.eJ, c.s2);

    vae_kernel<<<CS, TPB, SMEM_BYTES>>>(data_c, target_c, cond_emb,
                                        enc_Whh,
                                        hmu_W, hmu_b, cmu_W, cmu_b,
                                        fc1_W, fc1_b, fc2_W, fc2_b,
                                        dec_Whh,
                                        out_W, out_b,
                                        (float*)d_out, out_size);
    cudaStreamWaitEvent(0, c.eJ, 0);
}